// round 2
// baseline (speedup 1.0000x reference)
#include <cuda_runtime.h>
#include <math.h>

#define NDIM  256
#define NROT  32640
#define BATCH 65536

// ---------------- scratch (device globals; no allocation allowed) ----------
__device__ float2 g_cs1[NROT];
__device__ float2 g_cs2[NROT];
__device__ float  g_M1[NDIM * NDIM];   // row-major [r][c]
__device__ float  g_M2[NDIM * NDIM];
__device__ float  g_Wre[NDIM * NDIM];  // [n][k]  (M2 diag(cos) M1)
__device__ float  g_Wim[NDIM * NDIM];  // [n][k]  (M2 diag(sin) M1)
__device__ float  g_norm2[BATCH];

// ---------------- 1) cos/sin of all rotation angles ------------------------
__global__ void k_sincos(const float* __restrict__ rots1,
                         const float* __restrict__ rots2) {
    int i = blockIdx.x * blockDim.x + threadIdx.x;
    if (i < NROT) {
        float s, c;
        sincosf(rots1[i], &s, &c);
        g_cs1[i] = make_float2(c, s);
        sincosf(rots2[i], &s, &c);
        g_cs2[i] = make_float2(c, s);
    }
}

// ---------------- 2) build M1 / M2 column-wise ------------------------------
// One thread evolves one column of the matrix through all 32640 Givens
// rotations. Column state lives in shared memory (stride = 32 threads).
// Inner loop keeps v[i] (the row the whole i-phase keeps touching) in a
// register so the sequential dependency is one FFMA per rotation.
__global__ void k_build() {
    __shared__ float col[NDIM * 32];   // 32 KB: 32 columns x 256 rows
    int t = threadIdx.x;               // 0..31
    int mat = blockIdx.x >> 3;         // 0 -> M1, 1 -> M2
    int cbase = (blockIdx.x & 7) * 32;
    int c = cbase + t;

    const float2* __restrict__ cs = mat ? g_cs2 : g_cs1;
    float* __restrict__ M = mat ? g_M2 : g_M1;

    for (int r = 0; r < NDIM; ++r)
        col[r * 32 + t] = (r == c) ? 1.0f : 0.0f;
    // no syncs needed: each thread touches only its own column (index t)

    int ridx = 0;
    for (int i = 0; i < NDIM - 1; ++i) {
        float acc = col[i * 32 + t];
        #pragma unroll 4
        for (int j = i + 1; j < NDIM; ++j) {
            float2 v = __ldg(&cs[ridx]);
            ++ridx;
            float vj = col[j * 32 + t];
            col[j * 32 + t] = v.y * acc + v.x * vj;  // s*vi + c*vj
            acc = v.x * acc - v.y * vj;              // c*vi - s*vj
        }
        col[i * 32 + t] = acc;
    }

    for (int r = 0; r < NDIM; ++r)
        M[r * NDIM + c] = col[r * 32 + t];
}

// ---------------- 3) compose W = M2 diag(e^{i phi}) M1 ----------------------
// Wre[n][k] = sum_m M2[n][m] cos(ph[m]) M1[m][k]; Wim with sin.
__global__ void k_compose(const float* __restrict__ phases) {
    __shared__ float a[8][NDIM];
    __shared__ float b[8][NDIM];
    int t = threadIdx.x;          // 0..255  (= k, and = m for the fill)
    int n0 = blockIdx.x * 8;

    float sp, cp;
    sincosf(phases[t], &sp, &cp);
    #pragma unroll
    for (int r = 0; r < 8; ++r) {
        float m2 = g_M2[(n0 + r) * NDIM + t];
        a[r][t] = m2 * cp;
        b[r][t] = m2 * sp;
    }
    __syncthreads();

    float are[8], aim[8];
    #pragma unroll
    for (int r = 0; r < 8; ++r) { are[r] = 0.f; aim[r] = 0.f; }

    for (int m = 0; m < NDIM; ++m) {
        float m1 = g_M1[m * NDIM + t];
        #pragma unroll
        for (int r = 0; r < 8; ++r) {
            are[r] += a[r][m] * m1;
            aim[r] += b[r][m] * m1;
        }
    }
    #pragma unroll
    for (int r = 0; r < 8; ++r) {
        g_Wre[(n0 + r) * NDIM + t] = are[r];
        g_Wim[(n0 + r) * NDIM + t] = aim[r];
    }
}

// ---------------- 4) row squared norms --------------------------------------
__global__ void k_norm(const float4* __restrict__ x4) {
    int w = threadIdx.x >> 5;
    int lane = threadIdx.x & 31;
    int row = blockIdx.x * 4 + w;
    const float4* p = x4 + (size_t)row * 64;
    float4 va = p[lane];
    float4 vb = p[lane + 32];
    float s = va.x * va.x + va.y * va.y + va.z * va.z + va.w * va.w
            + vb.x * vb.x + vb.y * vb.y + vb.z * vb.z + vb.w * vb.w;
    #pragma unroll
    for (int o = 16; o; o >>= 1) s += __shfl_xor_sync(0xffffffffu, s, o);
    if (lane == 0) g_norm2[row] = s;
}

// ---------------- 5) big GEMM + fused |.|^2 / norm epilogue ------------------
// C-tile 128x64 per CTA, 256 threads, 8x4 micro-tile, two accumulators
// (re, im) per output. out[b][n] = (re^2 + im^2) / norm2[b].
__global__ __launch_bounds__(256) void k_gemm(const float* __restrict__ X,
                                              float* __restrict__ out) {
    __shared__ float Xs[128][33];    // [row][k]  (padded)
    __shared__ float Wr[32][68];     // [k][n]    (padded)
    __shared__ float Wi[32][68];

    int tid = threadIdx.x;
    int tx = tid & 15;               // 16 col-groups of 4
    int ty = tid >> 4;               // 16 row-groups of 8
    int mtile = blockIdx.x;          // 512
    int ntile = blockIdx.y;          // 4

    float ar[8][4], ai[8][4];
    #pragma unroll
    for (int i = 0; i < 8; ++i)
        #pragma unroll
        for (int j = 0; j < 4; ++j) { ar[i][j] = 0.f; ai[i][j] = 0.f; }

    const float4* __restrict__ X4 = (const float4*)X;
    const float4* __restrict__ Wre4 = (const float4*)g_Wre;
    const float4* __restrict__ Wim4 = (const float4*)g_Wim;

    for (int kc = 0; kc < 8; ++kc) {
        __syncthreads();
        // X tile: 128 rows x 32 k = 1024 float4
        #pragma unroll
        for (int u = 0; u < 4; ++u) {
            int li = u * 256 + tid;
            int r = li >> 3;
            int q = li & 7;
            float4 v = X4[(size_t)(mtile * 128 + r) * 64 + kc * 8 + q];
            Xs[r][q * 4 + 0] = v.x;
            Xs[r][q * 4 + 1] = v.y;
            Xs[r][q * 4 + 2] = v.z;
            Xs[r][q * 4 + 3] = v.w;
        }
        // W tiles: 64 n-rows x 32 k = 512 float4 each
        #pragma unroll
        for (int u = 0; u < 2; ++u) {
            int li = u * 256 + tid;
            int nl = li >> 3;
            int q = li & 7;
            int gi = (ntile * 64 + nl) * 64 + kc * 8 + q;
            float4 v = Wre4[gi];
            Wr[q * 4 + 0][nl] = v.x;
            Wr[q * 4 + 1][nl] = v.y;
            Wr[q * 4 + 2][nl] = v.z;
            Wr[q * 4 + 3][nl] = v.w;
            float4 w = Wim4[gi];
            Wi[q * 4 + 0][nl] = w.x;
            Wi[q * 4 + 1][nl] = w.y;
            Wi[q * 4 + 2][nl] = w.z;
            Wi[q * 4 + 3][nl] = w.w;
        }
        __syncthreads();

        #pragma unroll 4
        for (int k = 0; k < 32; ++k) {
            float xf[8];
            #pragma unroll
            for (int i = 0; i < 8; ++i) xf[i] = Xs[ty * 8 + i][k];
            float4 wr = *(const float4*)&Wr[k][tx * 4];
            float4 wi = *(const float4*)&Wi[k][tx * 4];
            #pragma unroll
            for (int i = 0; i < 8; ++i) {
                ar[i][0] += xf[i] * wr.x;
                ar[i][1] += xf[i] * wr.y;
                ar[i][2] += xf[i] * wr.z;
                ar[i][3] += xf[i] * wr.w;
                ai[i][0] += xf[i] * wi.x;
                ai[i][1] += xf[i] * wi.y;
                ai[i][2] += xf[i] * wi.z;
                ai[i][3] += xf[i] * wi.w;
            }
        }
    }

    // epilogue: |y|^2 / ||x||^2
    #pragma unroll
    for (int i = 0; i < 8; ++i) {
        int row = mtile * 128 + ty * 8 + i;
        float inv = 1.0f / g_norm2[row];
        float4 o;
        o.x = (ar[i][0] * ar[i][0] + ai[i][0] * ai[i][0]) * inv;
        o.y = (ar[i][1] * ar[i][1] + ai[i][1] * ai[i][1]) * inv;
        o.z = (ar[i][2] * ar[i][2] + ai[i][2] * ai[i][2]) * inv;
        o.w = (ar[i][3] * ar[i][3] + ai[i][3] * ai[i][3]) * inv;
        ((float4*)out)[(size_t)row * 64 + ntile * 16 + tx] = o;
    }
}

// ---------------- launcher ---------------------------------------------------
extern "C" void kernel_launch(void* const* d_in, const int* in_sizes, int n_in,
                              void* d_out, int out_size) {
    const float* x      = (const float*)d_in[0];
    const float* rots1  = (const float*)d_in[1];
    const float* phases = (const float*)d_in[2];
    const float* rots2  = (const float*)d_in[3];
    float* out = (float*)d_out;

    k_sincos<<<(NROT + 255) / 256, 256>>>(rots1, rots2);
    k_build<<<16, 32>>>();
    k_compose<<<NDIM / 8, NDIM>>>(phases);
    k_norm<<<BATCH / 4, 128>>>((const float4*)x);
    k_gemm<<<dim3(BATCH / 128, 4), 256>>>(x, out);
}

// round 8
// speedup vs baseline: 1.5892x; 1.5892x over previous
#include <cuda_runtime.h>
#include <cuda_bf16.h>
#include <stdint.h>
#include <math.h>

#define NDIM  256
#define NROT  32640
#define BATCH 65536

// ---------------- scratch (device globals; no allocation allowed) ----------
__device__ float2 g_cs1[NROT];
__device__ float2 g_cs2[NROT];
__device__ float  g_M1[NDIM * NDIM];   // row-major [r][c]
__device__ float  g_M2[NDIM * NDIM];
__device__ float  g_Wre[NDIM * NDIM];  // [n][k]
__device__ float  g_Wim[NDIM * NDIM];  // [n][k]
__device__ float  g_norm2[BATCH];

// bf16 split operands for the tensor-core GEMM
__device__ __nv_bfloat16 g_Xhi[BATCH * NDIM];        // 32 MB
__device__ __nv_bfloat16 g_Xlo[BATCH * NDIM];        // 32 MB
__device__ __nv_bfloat16 g_Whi[2 * NDIM * NDIM];     // N'=512 rows (even=Re, odd=Im)
__device__ __nv_bfloat16 g_Wlo[2 * NDIM * NDIM];

// ---------------- 1) cos/sin of all rotation angles ------------------------
__global__ void k_sincos(const float* __restrict__ rots1,
                         const float* __restrict__ rots2) {
    int i = blockIdx.x * blockDim.x + threadIdx.x;
    if (i < NROT) {
        float s, c;
        sincosf(rots1[i], &s, &c);
        g_cs1[i] = make_float2(c, s);
        sincosf(rots2[i], &s, &c);
        g_cs2[i] = make_float2(c, s);
    }
}

// ---------------- 2) build M1 / M2 column-wise ------------------------------
__global__ void k_build() {
    __shared__ float col[NDIM * 32];
    int t = threadIdx.x;               // 0..31
    int mat = blockIdx.x >> 3;
    int cbase = (blockIdx.x & 7) * 32;
    int c = cbase + t;

    const float2* __restrict__ cs = mat ? g_cs2 : g_cs1;
    float* __restrict__ M = mat ? g_M2 : g_M1;

    for (int r = 0; r < NDIM; ++r)
        col[r * 32 + t] = (r == c) ? 1.0f : 0.0f;

    int ridx = 0;
    for (int i = 0; i < NDIM - 1; ++i) {
        float acc = col[i * 32 + t];
        #pragma unroll 8
        for (int j = i + 1; j < NDIM; ++j) {
            float2 v = __ldg(&cs[ridx]);
            ++ridx;
            float vj = col[j * 32 + t];
            col[j * 32 + t] = v.y * acc + v.x * vj;
            acc = v.x * acc - v.y * vj;
        }
        col[i * 32 + t] = acc;
    }

    for (int r = 0; r < NDIM; ++r)
        M[r * NDIM + c] = col[r * 32 + t];
}

// ---------------- 3) compose W = M2 diag(e^{i phi}) M1 ----------------------
__global__ void k_compose(const float* __restrict__ phases) {
    __shared__ float sa[8][NDIM];
    __shared__ float sb[8][NDIM];
    int t = threadIdx.x;
    int n0 = blockIdx.x * 8;

    float sp, cp;
    sincosf(phases[t], &sp, &cp);
    #pragma unroll
    for (int r = 0; r < 8; ++r) {
        float m2 = g_M2[(n0 + r) * NDIM + t];
        sa[r][t] = m2 * cp;
        sb[r][t] = m2 * sp;
    }
    __syncthreads();

    float are[8], aim[8];
    #pragma unroll
    for (int r = 0; r < 8; ++r) { are[r] = 0.f; aim[r] = 0.f; }

    for (int m = 0; m < NDIM; ++m) {
        float m1 = g_M1[m * NDIM + t];
        #pragma unroll
        for (int r = 0; r < 8; ++r) {
            are[r] += sa[r][m] * m1;
            aim[r] += sb[r][m] * m1;
        }
    }
    #pragma unroll
    for (int r = 0; r < 8; ++r) {
        g_Wre[(n0 + r) * NDIM + t] = are[r];
        g_Wim[(n0 + r) * NDIM + t] = aim[r];
    }
}

// ---------------- 3b) split W (interleaved re/im) into bf16 hi/lo -----------
__global__ void k_convw() {
    int idx = blockIdx.x * 256 + threadIdx.x;   // 0 .. 131071
    int n2 = idx >> 8;
    int k  = idx & 255;
    const float* src = (n2 & 1) ? g_Wim : g_Wre;
    float v = src[(n2 >> 1) * NDIM + k];
    __nv_bfloat16 h = __float2bfloat16(v);
    float lo = v - __bfloat162float(h);
    g_Whi[idx] = h;
    g_Wlo[idx] = __float2bfloat16(lo);
}

// ---------------- 3c) split X into bf16 hi/lo --------------------------------
__global__ void k_convx(const float4* __restrict__ x4) {
    int i = blockIdx.x * 256 + threadIdx.x;     // < BATCH*NDIM/4
    float4 v = x4[i];
    __nv_bfloat16 h0 = __float2bfloat16(v.x);
    __nv_bfloat16 h1 = __float2bfloat16(v.y);
    __nv_bfloat16 h2 = __float2bfloat16(v.z);
    __nv_bfloat16 h3 = __float2bfloat16(v.w);
    __nv_bfloat16 l0 = __float2bfloat16(v.x - __bfloat162float(h0));
    __nv_bfloat16 l1 = __float2bfloat16(v.y - __bfloat162float(h1));
    __nv_bfloat16 l2 = __float2bfloat16(v.z - __bfloat162float(h2));
    __nv_bfloat16 l3 = __float2bfloat16(v.w - __bfloat162float(h3));
    __nv_bfloat162* Ph = (__nv_bfloat162*)g_Xhi;
    __nv_bfloat162* Pl = (__nv_bfloat162*)g_Xlo;
    Ph[i * 2 + 0] = __nv_bfloat162(h0, h1);
    Ph[i * 2 + 1] = __nv_bfloat162(h2, h3);
    Pl[i * 2 + 0] = __nv_bfloat162(l0, l1);
    Pl[i * 2 + 1] = __nv_bfloat162(l2, l3);
}

// ---------------- 4) row squared norms --------------------------------------
__global__ void k_norm(const float4* __restrict__ x4) {
    int w = threadIdx.x >> 5;
    int lane = threadIdx.x & 31;
    int row = blockIdx.x * 4 + w;
    const float4* p = x4 + (size_t)row * 64;
    float4 va = p[lane];
    float4 vb = p[lane + 32];
    float s = va.x * va.x + va.y * va.y + va.z * va.z + va.w * va.w
            + vb.x * vb.x + vb.y * vb.y + vb.z * vb.z + vb.w * vb.w;
    #pragma unroll
    for (int o = 16; o; o >>= 1) s += __shfl_xor_sync(0xffffffffu, s, o);
    if (lane == 0) g_norm2[row] = s;
}

// ---------------- 5) tensor-core GEMM + fused |.|^2 / norm epilogue ----------
__device__ __forceinline__ void mma16816(float* d, const uint32_t* a,
                                         uint32_t b0, uint32_t b1) {
    asm volatile(
        "mma.sync.aligned.m16n8k16.row.col.f32.bf16.bf16.f32 "
        "{%0,%1,%2,%3}, {%4,%5,%6,%7}, {%8,%9}, {%0,%1,%2,%3};"
        : "+f"(d[0]), "+f"(d[1]), "+f"(d[2]), "+f"(d[3])
        : "r"(a[0]), "r"(a[1]), "r"(a[2]), "r"(a[3]), "r"(b0), "r"(b1));
}

__device__ __forceinline__ void ldsm_x4(uint32_t& r0, uint32_t& r1,
                                        uint32_t& r2, uint32_t& r3,
                                        uint32_t addr) {
    asm volatile("ldmatrix.sync.aligned.m8n8.x4.shared.b16 {%0,%1,%2,%3}, [%4];"
                 : "=r"(r0), "=r"(r1), "=r"(r2), "=r"(r3) : "r"(addr));
}

// C-tile 128(M) x 128(N'), 8 warps (2x4), warp tile 64x32, BK=32.
// K accumulation: 3 phases (Xhi*Whi, Xhi*Wlo, Xlo*Whi) x K=256.
// N' interleaves re/im: even col = re, odd = im -> out col = n'/2.
// NOTE: B (W, stored [n][k] k-contiguous) is loaded with NON-trans ldmatrix —
// that layout is already col-major B for mma .row.col.
__global__ __launch_bounds__(256, 2) void k_gemm_tc(float* __restrict__ out) {
    __shared__ __align__(16) __nv_bfloat16 As[128 * 40];   // stride 40 pads banks
    __shared__ __align__(16) __nv_bfloat16 Bs[128 * 40];

    int tid = threadIdx.x;
    int wid = tid >> 5, lane = tid & 31;
    int warp_m = wid >> 2;          // 0..1
    int warp_n = wid & 3;           // 0..3
    int mtile = blockIdx.x;         // 0..511
    int ntile = blockIdx.y;         // 0..3

    float acc[4][4][4];
    #pragma unroll
    for (int mt = 0; mt < 4; ++mt)
        #pragma unroll
        for (int nt = 0; nt < 4; ++nt)
            #pragma unroll
            for (int q = 0; q < 4; ++q) acc[mt][nt][q] = 0.f;

    uint32_t as_base = (uint32_t)__cvta_generic_to_shared(As);
    uint32_t bs_base = (uint32_t)__cvta_generic_to_shared(Bs);

    // ldmatrix lane addressing (non-trans for both operands)
    int a_row  = warp_m * 64 + (lane & 15);         // m rows
    int a_colp = (lane >> 4) * 8;                   // k half
    int b_rowl = ((lane >> 4) << 3) + (lane & 7);   // n rows: 0-7,0-7,8-15,8-15
    int b_colp = ((lane >> 3) & 1) * 8;             // k half: 0,8,0,8

    // global->smem staging indices
    int ld_row = tid >> 2;          // 0..63
    int ld_chk = tid & 3;           // 0..3 (8 bf16 each)

    for (int it = 0; it < 24; ++it) {
        int phase = it >> 3;
        int kc = (it & 7) << 5;
        const uint4* Ap = (phase == 2) ? (const uint4*)g_Xlo : (const uint4*)g_Xhi;
        const uint4* Bp = (phase == 1) ? (const uint4*)g_Wlo : (const uint4*)g_Whi;

        __syncthreads();
        {
            const uint4* ap = Ap + (size_t)(mtile * 128 + ld_row) * 32 + (kc >> 3) + ld_chk;
            uint4 v0 = ap[0];
            uint4 v1 = ap[64 * 32];
            *(uint4*)&As[ld_row * 40 + ld_chk * 8] = v0;
            *(uint4*)&As[(ld_row + 64) * 40 + ld_chk * 8] = v1;
            const uint4* bp = Bp + (size_t)(ntile * 128 + ld_row) * 32 + (kc >> 3) + ld_chk;
            uint4 w0 = bp[0];
            uint4 w1 = bp[64 * 32];
            *(uint4*)&Bs[ld_row * 40 + ld_chk * 8] = w0;
            *(uint4*)&Bs[(ld_row + 64) * 40 + ld_chk * 8] = w1;
        }
        __syncthreads();

        #pragma unroll
        for (int kk = 0; kk < 2; ++kk) {
            uint32_t afrag[4][4];
            #pragma unroll
            for (int mt = 0; mt < 4; ++mt) {
                uint32_t addr = as_base +
                    (uint32_t)(((a_row + mt * 16) * 40 + kk * 16 + a_colp) * 2);
                ldsm_x4(afrag[mt][0], afrag[mt][1], afrag[mt][2], afrag[mt][3], addr);
            }
            uint32_t bfrag[2][4];
            #pragma unroll
            for (int nb = 0; nb < 2; ++nb) {
                uint32_t addr = bs_base +
                    (uint32_t)(((warp_n * 32 + nb * 16 + b_rowl) * 40 + kk * 16 + b_colp) * 2);
                ldsm_x4(bfrag[nb][0], bfrag[nb][1], bfrag[nb][2], bfrag[nb][3], addr);
            }
            #pragma unroll
            for (int mt = 0; mt < 4; ++mt)
                #pragma unroll
                for (int nt = 0; nt < 4; ++nt)
                    mma16816(acc[mt][nt], afrag[mt],
                             bfrag[nt >> 1][(nt & 1) * 2],
                             bfrag[nt >> 1][(nt & 1) * 2 + 1]);
        }
    }

    // epilogue: pair (even,odd) N' columns -> |y|^2 / ||x||^2
    int r0 = mtile * 128 + warp_m * 64 + (lane >> 2);
    int cb = ntile * 64 + warp_n * 16 + (lane & 3);
    #pragma unroll
    for (int mt = 0; mt < 4; ++mt) {
        int row = r0 + mt * 16;
        float inv0 = 1.0f / g_norm2[row];
        float inv8 = 1.0f / g_norm2[row + 8];
        #pragma unroll
        for (int nt = 0; nt < 4; ++nt) {
            int colc = cb + nt * 4;
            float* dd = acc[mt][nt];
            out[(size_t)row * NDIM + colc]       = (dd[0] * dd[0] + dd[1] * dd[1]) * inv0;
            out[(size_t)(row + 8) * NDIM + colc] = (dd[2] * dd[2] + dd[3] * dd[3]) * inv8;
        }
    }
}

// ---------------- launcher ---------------------------------------------------
extern "C" void kernel_launch(void* const* d_in, const int* in_sizes, int n_in,
                              void* d_out, int out_size) {
    const float* x      = (const float*)d_in[0];
    const float* rots1  = (const float*)d_in[1];
    const float* phases = (const float*)d_in[2];
    const float* rots2  = (const float*)d_in[3];
    float* out = (float*)d_out;

    k_sincos<<<(NROT + 255) / 256, 256>>>(rots1, rots2);
    k_build<<<16, 32>>>();
    k_compose<<<NDIM / 8, NDIM>>>(phases);
    k_convw<<<512, 256>>>();
    k_convx<<<BATCH * NDIM / 4 / 256, 256>>>((const float4*)x);
    k_norm<<<BATCH / 4, 128>>>((const float4*)x);
    k_gemm_tc<<<dim3(BATCH / 128, 4), 256>>>(out);
}

// round 10
// speedup vs baseline: 4.3774x; 2.7544x over previous
#include <cuda_runtime.h>
#include <cuda_bf16.h>
#include <stdint.h>
#include <math.h>

#define NDIM  256
#define NROT  32640
#define BATCH 65536

// ---------------- scratch (device globals; no allocation allowed) ----------
__device__ float2 g_cs1[NROT];
__device__ float2 g_cs2[NROT];
__device__ float  g_chunks[2 * 8 * NDIM * NDIM];   // 4 MB chunk products
__device__ float  g_q[2 * 4 * NDIM * NDIM];        // 2 MB
__device__ float  g_r[2 * 2 * NDIM * NDIM];        // 1 MB
__device__ float  g_M1[NDIM * NDIM];
__device__ float  g_M2[NDIM * NDIM];
__device__ float  g_Wre[NDIM * NDIM];
__device__ float  g_Wim[NDIM * NDIM];
__device__ float  g_norm2[BATCH];

__device__ __nv_bfloat16 g_Xhi[BATCH * NDIM];
__device__ __nv_bfloat16 g_Xlo[BATCH * NDIM];
__device__ __nv_bfloat16 g_Whi[2 * NDIM * NDIM];   // N'=512 (even=Re, odd=Im)
__device__ __nv_bfloat16 g_Wlo[2 * NDIM * NDIM];

// chunk boundaries (phase index space, 9 entries -> 8 chunks, ~4080 rots each)
__constant__ int c_bound[9] = {0, 16, 34, 53, 74, 99, 127, 165, 255};

// ---------------- 1) cos/sin --------------------------------------------------
__global__ void k_sincos(const float* __restrict__ rots1,
                         const float* __restrict__ rots2) {
    int i = blockIdx.x * blockDim.x + threadIdx.x;
    if (i < NROT) {
        float s, c;
        sincosf(rots1[i], &s, &c);
        g_cs1[i] = make_float2(c, s);
        sincosf(rots2[i], &s, &c);
        g_cs2[i] = make_float2(c, s);
    }
}

// ---------------- 2a) build 8 chunk products per matrix ----------------------
__global__ void k_build_chunk() {
    __shared__ float col[NDIM * 32];
    int t = threadIdx.x;
    int b = blockIdx.x;
    int mat = b >> 6;
    int rem = b & 63;
    int chunk = rem >> 3;
    int cg = rem & 7;
    int c = cg * 32 + t;

    int a = c_bound[chunk];
    int e = c_bound[chunk + 1];

    const float2* __restrict__ cs = mat ? g_cs2 : g_cs1;
    float* __restrict__ P = g_chunks + (size_t)(mat * 8 + chunk) * (NDIM * NDIM);

    for (int r = 0; r < NDIM; ++r)
        col[r * 32 + t] = (r == c) ? 1.0f : 0.0f;

    int ridx = a * 255 - (a * (a - 1)) / 2;
    for (int i = a; i < e; ++i) {
        float acc = col[i * 32 + t];
        #pragma unroll 8
        for (int j = i + 1; j < NDIM; ++j) {
            float2 v = __ldg(&cs[ridx]);
            ++ridx;
            float vj = col[j * 32 + t];
            col[j * 32 + t] = v.y * acc + v.x * vj;
            acc = v.x * acc - v.y * vj;
        }
        col[i * 32 + t] = acc;
    }

    for (int r = 0; r < NDIM; ++r)
        P[r * NDIM + c] = col[r * 32 + t];
}

// ---------------- 2b) combine chunks: C = A(later) * B(earlier) --------------
// grid (4,4,z): 64x64 C tile per CTA, 256 threads, 4x4 outputs/thread, K=256.
// NOTE: smem tiles are padded (stride 33 / 65 floats) -> row stride is NOT
// 16B-aligned, so stores must be scalar floats (float4 stores trap).
__global__ __launch_bounds__(256) void k_combine(int step) {
    __shared__ float Asm[64][33];
    __shared__ float Bsm[32][65];

    int z = blockIdx.z;
    const float *A, *B;
    float* C;
    if (step == 0) {
        int mat = z >> 2, p = z & 3;
        A = g_chunks + (size_t)(mat * 8 + 2 * p + 1) * (NDIM * NDIM);
        B = g_chunks + (size_t)(mat * 8 + 2 * p) * (NDIM * NDIM);
        C = g_q + (size_t)(mat * 4 + p) * (NDIM * NDIM);
    } else if (step == 1) {
        int mat = z >> 1, p = z & 1;
        A = g_q + (size_t)(mat * 4 + 2 * p + 1) * (NDIM * NDIM);
        B = g_q + (size_t)(mat * 4 + 2 * p) * (NDIM * NDIM);
        C = g_r + (size_t)(mat * 2 + p) * (NDIM * NDIM);
    } else {
        int mat = z;
        A = g_r + (size_t)(mat * 2 + 1) * (NDIM * NDIM);
        B = g_r + (size_t)(mat * 2 + 0) * (NDIM * NDIM);
        C = mat ? g_M2 : g_M1;
    }

    int tid = threadIdx.x;
    int tx = tid & 15, ty = tid >> 4;
    int row0 = blockIdx.y * 64;
    int col0 = blockIdx.x * 64;

    float acc[4][4];
    #pragma unroll
    for (int i = 0; i < 4; ++i)
        #pragma unroll
        for (int j = 0; j < 4; ++j) acc[i][j] = 0.f;

    for (int kc = 0; kc < 8; ++kc) {
        __syncthreads();
        {   // A tile 64 x 32 (scalar stores: padded stride not 16B-aligned)
            int r = tid >> 2, q = tid & 3;
            const float4* ap = (const float4*)&A[(row0 + r) * NDIM + kc * 32];
            float4 v0 = ap[q * 2], v1 = ap[q * 2 + 1];
            Asm[r][q * 8 + 0] = v0.x; Asm[r][q * 8 + 1] = v0.y;
            Asm[r][q * 8 + 2] = v0.z; Asm[r][q * 8 + 3] = v0.w;
            Asm[r][q * 8 + 4] = v1.x; Asm[r][q * 8 + 5] = v1.y;
            Asm[r][q * 8 + 6] = v1.z; Asm[r][q * 8 + 7] = v1.w;
        }
        {   // B tile 32 x 64
            int r = tid >> 3, q = tid & 7;
            const float4* bp = (const float4*)&B[(kc * 32 + r) * NDIM + col0];
            float4 v0 = bp[q * 2], v1 = bp[q * 2 + 1];
            Bsm[r][q * 8 + 0] = v0.x; Bsm[r][q * 8 + 1] = v0.y;
            Bsm[r][q * 8 + 2] = v0.z; Bsm[r][q * 8 + 3] = v0.w;
            Bsm[r][q * 8 + 4] = v1.x; Bsm[r][q * 8 + 5] = v1.y;
            Bsm[r][q * 8 + 6] = v1.z; Bsm[r][q * 8 + 7] = v1.w;
        }
        __syncthreads();

        #pragma unroll 8
        for (int m = 0; m < 32; ++m) {
            float ar[4], br[4];
            #pragma unroll
            for (int i = 0; i < 4; ++i) ar[i] = Asm[ty * 4 + i][m];
            #pragma unroll
            for (int j = 0; j < 4; ++j) br[j] = Bsm[m][tx * 4 + j];
            #pragma unroll
            for (int i = 0; i < 4; ++i)
                #pragma unroll
                for (int j = 0; j < 4; ++j) acc[i][j] += ar[i] * br[j];
        }
    }

    #pragma unroll
    for (int i = 0; i < 4; ++i)
        #pragma unroll
        for (int j = 0; j < 4; ++j)
            C[(size_t)(row0 + ty * 4 + i) * NDIM + col0 + tx * 4 + j] = acc[i][j];
}

// ---------------- 3) compose W = M2 diag(e^{i phi}) M1 -----------------------
__global__ void k_compose(const float* __restrict__ phases) {
    __shared__ float sa[8][NDIM];
    __shared__ float sb[8][NDIM];
    int t = threadIdx.x;
    int n0 = blockIdx.x * 8;

    float sp, cp;
    sincosf(phases[t], &sp, &cp);
    #pragma unroll
    for (int r = 0; r < 8; ++r) {
        float m2 = g_M2[(n0 + r) * NDIM + t];
        sa[r][t] = m2 * cp;
        sb[r][t] = m2 * sp;
    }
    __syncthreads();

    float are[8], aim[8];
    #pragma unroll
    for (int r = 0; r < 8; ++r) { are[r] = 0.f; aim[r] = 0.f; }

    for (int m = 0; m < NDIM; ++m) {
        float m1 = g_M1[m * NDIM + t];
        #pragma unroll
        for (int r = 0; r < 8; ++r) {
            are[r] += sa[r][m] * m1;
            aim[r] += sb[r][m] * m1;
        }
    }
    #pragma unroll
    for (int r = 0; r < 8; ++r) {
        g_Wre[(n0 + r) * NDIM + t] = are[r];
        g_Wim[(n0 + r) * NDIM + t] = aim[r];
    }
}

// ---------------- 3b) split W into bf16 hi/lo (re/im interleaved) ------------
__global__ void k_convw() {
    int idx = blockIdx.x * 256 + threadIdx.x;
    int n2 = idx >> 8;
    int k  = idx & 255;
    const float* src = (n2 & 1) ? g_Wim : g_Wre;
    float v = src[(n2 >> 1) * NDIM + k];
    __nv_bfloat16 h = __float2bfloat16(v);
    float lo = v - __bfloat162float(h);
    g_Whi[idx] = h;
    g_Wlo[idx] = __float2bfloat16(lo);
}

// ---------------- 4) fused X split + row norms (one X read) ------------------
__global__ void k_convx_norm(const float4* __restrict__ x4) {
    int w = threadIdx.x >> 5;
    int lane = threadIdx.x & 31;
    int row = blockIdx.x * 8 + w;
    const float4* p = x4 + (size_t)row * 64;
    float4 va = p[lane];
    float4 vb = p[lane + 32];

    float s = va.x * va.x + va.y * va.y + va.z * va.z + va.w * va.w
            + vb.x * vb.x + vb.y * vb.y + vb.z * vb.z + vb.w * vb.w;
    #pragma unroll
    for (int o = 16; o; o >>= 1) s += __shfl_xor_sync(0xffffffffu, s, o);
    if (lane == 0) g_norm2[row] = s;

    __nv_bfloat162* Ph = (__nv_bfloat162*)(g_Xhi + (size_t)row * NDIM);
    __nv_bfloat162* Pl = (__nv_bfloat162*)(g_Xlo + (size_t)row * NDIM);
    #pragma unroll
    for (int half = 0; half < 2; ++half) {
        float4 v = half ? vb : va;
        int base = (lane + half * 32) * 2;
        __nv_bfloat16 h0 = __float2bfloat16(v.x);
        __nv_bfloat16 h1 = __float2bfloat16(v.y);
        __nv_bfloat16 h2 = __float2bfloat16(v.z);
        __nv_bfloat16 h3 = __float2bfloat16(v.w);
        Ph[base + 0] = __nv_bfloat162(h0, h1);
        Ph[base + 1] = __nv_bfloat162(h2, h3);
        Pl[base + 0] = __nv_bfloat162(__float2bfloat16(v.x - __bfloat162float(h0)),
                                      __float2bfloat16(v.y - __bfloat162float(h1)));
        Pl[base + 1] = __nv_bfloat162(__float2bfloat16(v.z - __bfloat162float(h2)),
                                      __float2bfloat16(v.w - __bfloat162float(h3)));
    }
}

// ---------------- 5) tensor-core GEMM, double-buffered cp.async --------------
__device__ __forceinline__ void mma16816(float* d, const uint32_t* a,
                                         uint32_t b0, uint32_t b1) {
    asm volatile(
        "mma.sync.aligned.m16n8k16.row.col.f32.bf16.bf16.f32 "
        "{%0,%1,%2,%3}, {%4,%5,%6,%7}, {%8,%9}, {%0,%1,%2,%3};"
        : "+f"(d[0]), "+f"(d[1]), "+f"(d[2]), "+f"(d[3])
        : "r"(a[0]), "r"(a[1]), "r"(a[2]), "r"(a[3]), "r"(b0), "r"(b1));
}

__device__ __forceinline__ void ldsm_x4(uint32_t& r0, uint32_t& r1,
                                        uint32_t& r2, uint32_t& r3,
                                        uint32_t addr) {
    asm volatile("ldmatrix.sync.aligned.m8n8.x4.shared.b16 {%0,%1,%2,%3}, [%4];"
                 : "=r"(r0), "=r"(r1), "=r"(r2), "=r"(r3) : "r"(addr));
}

__device__ __forceinline__ void cp16(uint32_t dst, const void* src) {
    asm volatile("cp.async.cg.shared.global [%0], [%1], 16;" :: "r"(dst), "l"(src));
}
__device__ __forceinline__ void cp_commit() {
    asm volatile("cp.async.commit_group;");
}
template <int N>
__device__ __forceinline__ void cp_wait() {
    asm volatile("cp.async.wait_group %0;" :: "n"(N));
}

// C-tile 128(M) x 128(N'), 8 warps, warp tile 64x32, BK=32, 24 stages
// (3 split-phases x 8 k-chunks), 2-deep cp.async pipeline.
__global__ __launch_bounds__(256, 2) void k_gemm_tc(float* __restrict__ out) {
    __shared__ __align__(16) __nv_bfloat16 As[2][128 * 40];
    __shared__ __align__(16) __nv_bfloat16 Bs[2][128 * 40];

    int tid = threadIdx.x;
    int wid = tid >> 5, lane = tid & 31;
    int warp_m = wid >> 2;
    int warp_n = wid & 3;
    int mtile = blockIdx.x;
    int ntile = blockIdx.y;

    float acc[4][4][4];
    #pragma unroll
    for (int mt = 0; mt < 4; ++mt)
        #pragma unroll
        for (int nt = 0; nt < 4; ++nt)
            #pragma unroll
            for (int q = 0; q < 4; ++q) acc[mt][nt][q] = 0.f;

    uint32_t as_base = (uint32_t)__cvta_generic_to_shared(&As[0][0]);
    uint32_t bs_base = (uint32_t)__cvta_generic_to_shared(&Bs[0][0]);

    int a_row  = warp_m * 64 + (lane & 15);
    int a_colp = (lane >> 4) * 8;
    int b_rowl = ((lane >> 4) << 3) + (lane & 7);
    int b_colp = ((lane >> 3) & 1) * 8;

    int ld_row = tid >> 2;
    int ld_chk = tid & 3;
    uint32_t sa0 = (uint32_t)((ld_row * 40 + ld_chk * 8) * 2);
    uint32_t sa1 = (uint32_t)(((ld_row + 64) * 40 + ld_chk * 8) * 2);

    auto load_stage = [&](int it, int buf) {
        int phase = it >> 3;
        int kc8 = (it & 7) << 2;
        const uint4* Ap = (phase == 2) ? (const uint4*)g_Xlo : (const uint4*)g_Xhi;
        const uint4* Bp = (phase == 1) ? (const uint4*)g_Wlo : (const uint4*)g_Whi;
        const uint4* ap = Ap + (size_t)(mtile * 128 + ld_row) * 32 + kc8 + ld_chk;
        const uint4* bp = Bp + (size_t)(ntile * 128 + ld_row) * 32 + kc8 + ld_chk;
        uint32_t ab = as_base + (uint32_t)buf * 10240;
        uint32_t bb = bs_base + (uint32_t)buf * 10240;
        cp16(ab + sa0, ap);
        cp16(ab + sa1, ap + 64 * 32);
        cp16(bb + sa0, bp);
        cp16(bb + sa1, bp + 64 * 32);
    };

    load_stage(0, 0);
    cp_commit();

    for (int it = 0; it < 24; ++it) {
        int buf = it & 1;
        if (it + 1 < 24) {
            load_stage(it + 1, buf ^ 1);
            cp_commit();
            cp_wait<1>();
        } else {
            cp_wait<0>();
        }
        __syncthreads();

        uint32_t abuf = as_base + (uint32_t)buf * 10240;
        uint32_t bbuf = bs_base + (uint32_t)buf * 10240;
        #pragma unroll
        for (int kk = 0; kk < 2; ++kk) {
            uint32_t afrag[4][4];
            #pragma unroll
            for (int mt = 0; mt < 4; ++mt) {
                uint32_t addr = abuf +
                    (uint32_t)(((a_row + mt * 16) * 40 + kk * 16 + a_colp) * 2);
                ldsm_x4(afrag[mt][0], afrag[mt][1], afrag[mt][2], afrag[mt][3], addr);
            }
            uint32_t bfrag[2][4];
            #pragma unroll
            for (int nb = 0; nb < 2; ++nb) {
                uint32_t addr = bbuf +
                    (uint32_t)(((warp_n * 32 + nb * 16 + b_rowl) * 40 + kk * 16 + b_colp) * 2);
                ldsm_x4(bfrag[nb][0], bfrag[nb][1], bfrag[nb][2], bfrag[nb][3], addr);
            }
            #pragma unroll
            for (int mt = 0; mt < 4; ++mt)
                #pragma unroll
                for (int nt = 0; nt < 4; ++nt)
                    mma16816(acc[mt][nt], afrag[mt],
                             bfrag[nt >> 1][(nt & 1) * 2],
                             bfrag[nt >> 1][(nt & 1) * 2 + 1]);
        }
        __syncthreads();
    }

    // epilogue: pair (even,odd) N' columns -> |y|^2 / ||x||^2
    int r0 = mtile * 128 + warp_m * 64 + (lane >> 2);
    int cb = ntile * 64 + warp_n * 16 + (lane & 3);
    #pragma unroll
    for (int mt = 0; mt < 4; ++mt) {
        int row = r0 + mt * 16;
        float inv0 = 1.0f / g_norm2[row];
        float inv8 = 1.0f / g_norm2[row + 8];
        #pragma unroll
        for (int nt = 0; nt < 4; ++nt) {
            int colc = cb + nt * 4;
            float* dd = acc[mt][nt];
            out[(size_t)row * NDIM + colc]       = (dd[0] * dd[0] + dd[1] * dd[1]) * inv0;
            out[(size_t)(row + 8) * NDIM + colc] = (dd[2] * dd[2] + dd[3] * dd[3]) * inv8;
        }
    }
}

// ---------------- launcher ---------------------------------------------------
extern "C" void kernel_launch(void* const* d_in, const int* in_sizes, int n_in,
                              void* d_out, int out_size) {
    const float* x      = (const float*)d_in[0];
    const float* rots1  = (const float*)d_in[1];
    const float* phases = (const float*)d_in[2];
    const float* rots2  = (const float*)d_in[3];
    float* out = (float*)d_out;

    k_sincos<<<(NROT + 255) / 256, 256>>>(rots1, rots2);
    k_build_chunk<<<128, 32>>>();
    k_combine<<<dim3(4, 4, 8), 256>>>(0);
    k_combine<<<dim3(4, 4, 4), 256>>>(1);
    k_combine<<<dim3(4, 4, 2), 256>>>(2);
    k_compose<<<NDIM / 8, NDIM>>>(phases);
    k_convw<<<512, 256>>>();
    k_convx_norm<<<BATCH / 8, 256>>>((const float4*)x);
    k_gemm_tc<<<dim3(BATCH / 128, 4), 256>>>(out);
}

// round 13
// speedup vs baseline: 4.7192x; 1.0781x over previous
#include <cuda_runtime.h>
#include <cuda_bf16.h>
#include <stdint.h>
#include <math.h>

#define NDIM  256
#define NROT  32640
#define BATCH 65536

// ---------------- scratch (device globals; no allocation allowed) ----------
__device__ float2 g_cs1[NROT];
__device__ float2 g_cs2[NROT];
__device__ float  g_chunks[2 * 8 * NDIM * NDIM];
__device__ float  g_q[2 * 4 * NDIM * NDIM];
__device__ float  g_r[2 * 2 * NDIM * NDIM];
__device__ float  g_M1[NDIM * NDIM];
__device__ float  g_M2[NDIM * NDIM];
__device__ float  g_Wre[NDIM * NDIM];
__device__ float  g_Wim[NDIM * NDIM];
__device__ float  g_norm2[BATCH];

__device__ __nv_bfloat16 g_Xhi[BATCH * NDIM];
__device__ __nv_bfloat16 g_Xlo[BATCH * NDIM];
__device__ __nv_bfloat16 g_Whi[2 * NDIM * NDIM];   // N'=512 (even=Re, odd=Im)
__device__ __nv_bfloat16 g_Wlo[2 * NDIM * NDIM];

__constant__ int c_bound[9] = {0, 16, 34, 53, 74, 99, 127, 165, 255};

// ---------------- PTX helpers ------------------------------------------------
__device__ __forceinline__ uint32_t smem_u32(const void* p) {
    uint32_t a;
    asm("{ .reg .u64 t; cvta.to.shared.u64 t, %1; cvt.u32.u64 %0, t; }"
        : "=r"(a) : "l"(p));
    return a;
}

__device__ __forceinline__ void cp16(uint32_t dst, const void* src) {
    asm volatile("cp.async.cg.shared.global [%0], [%1], 16;" :: "r"(dst), "l"(src));
}
__device__ __forceinline__ void cp_commit() {
    asm volatile("cp.async.commit_group;");
}
template <int N>
__device__ __forceinline__ void cp_wait() {
    asm volatile("cp.async.wait_group %0;" :: "n"(N));
}

__device__ __forceinline__ void mma16816(float* d, const uint32_t* a,
                                         uint32_t b0, uint32_t b1) {
    asm volatile(
        "mma.sync.aligned.m16n8k16.row.col.f32.bf16.bf16.f32 "
        "{%0,%1,%2,%3}, {%4,%5,%6,%7}, {%8,%9}, {%0,%1,%2,%3};"
        : "+f"(d[0]), "+f"(d[1]), "+f"(d[2]), "+f"(d[3])
        : "r"(a[0]), "r"(a[1]), "r"(a[2]), "r"(a[3]), "r"(b0), "r"(b1));
}

__device__ __forceinline__ void ldsm_x4(uint32_t& r0, uint32_t& r1,
                                        uint32_t& r2, uint32_t& r3,
                                        uint32_t addr) {
    asm volatile("ldmatrix.sync.aligned.m8n8.x4.shared.b16 {%0,%1,%2,%3}, [%4];"
                 : "=r"(r0), "=r"(r1), "=r"(r2), "=r"(r3) : "r"(addr));
}

// ---------------- 1) cos/sin --------------------------------------------------
__global__ void k_sincos(const float* __restrict__ rots1,
                         const float* __restrict__ rots2) {
    int i = blockIdx.x * blockDim.x + threadIdx.x;
    if (i < NROT) {
        float s, c;
        sincosf(rots1[i], &s, &c);
        g_cs1[i] = make_float2(c, s);
        sincosf(rots2[i], &s, &c);
        g_cs2[i] = make_float2(c, s);
    }
}

// ---------------- 2a) build 8 chunk products per matrix ----------------------
__global__ void k_build_chunk() {
    __shared__ float col[NDIM * 32];
    int t = threadIdx.x;
    int b = blockIdx.x;
    int mat = b >> 6;
    int rem = b & 63;
    int chunk = rem >> 3;
    int cg = rem & 7;
    int c = cg * 32 + t;

    int a = c_bound[chunk];
    int e = c_bound[chunk + 1];

    const float2* __restrict__ cs = mat ? g_cs2 : g_cs1;
    float* __restrict__ P = g_chunks + (size_t)(mat * 8 + chunk) * (NDIM * NDIM);

    for (int r = 0; r < NDIM; ++r)
        col[r * 32 + t] = (r == c) ? 1.0f : 0.0f;

    int ridx = a * 255 - (a * (a - 1)) / 2;
    for (int i = a; i < e; ++i) {
        float acc = col[i * 32 + t];
        #pragma unroll 8
        for (int j = i + 1; j < NDIM; ++j) {
            float2 v = __ldg(&cs[ridx]);
            ++ridx;
            float vj = col[j * 32 + t];
            col[j * 32 + t] = v.y * acc + v.x * vj;
            acc = v.x * acc - v.y * vj;
        }
        col[i * 32 + t] = acc;
    }

    for (int r = 0; r < NDIM; ++r)
        P[r * NDIM + c] = col[r * 32 + t];
}

// ---------------- 2b) combine chunks (fp32, scalar smem stores) --------------
__global__ __launch_bounds__(256) void k_combine(int step) {
    __shared__ float Asm[64][33];
    __shared__ float Bsm[32][65];

    int z = blockIdx.z;
    const float *A, *B;
    float* C;
    if (step == 0) {
        int mat = z >> 2, p = z & 3;
        A = g_chunks + (size_t)(mat * 8 + 2 * p + 1) * (NDIM * NDIM);
        B = g_chunks + (size_t)(mat * 8 + 2 * p) * (NDIM * NDIM);
        C = g_q + (size_t)(mat * 4 + p) * (NDIM * NDIM);
    } else if (step == 1) {
        int mat = z >> 1, p = z & 1;
        A = g_q + (size_t)(mat * 4 + 2 * p + 1) * (NDIM * NDIM);
        B = g_q + (size_t)(mat * 4 + 2 * p) * (NDIM * NDIM);
        C = g_r + (size_t)(mat * 2 + p) * (NDIM * NDIM);
    } else {
        int mat = z;
        A = g_r + (size_t)(mat * 2 + 1) * (NDIM * NDIM);
        B = g_r + (size_t)(mat * 2 + 0) * (NDIM * NDIM);
        C = mat ? g_M2 : g_M1;
    }

    int tid = threadIdx.x;
    int tx = tid & 15, ty = tid >> 4;
    int row0 = blockIdx.y * 64;
    int col0 = blockIdx.x * 64;

    float acc[4][4];
    #pragma unroll
    for (int i = 0; i < 4; ++i)
        #pragma unroll
        for (int j = 0; j < 4; ++j) acc[i][j] = 0.f;

    for (int kc = 0; kc < 8; ++kc) {
        __syncthreads();
        {
            int r = tid >> 2, q = tid & 3;
            const float4* ap = (const float4*)&A[(row0 + r) * NDIM + kc * 32];
            float4 v0 = ap[q * 2], v1 = ap[q * 2 + 1];
            Asm[r][q * 8 + 0] = v0.x; Asm[r][q * 8 + 1] = v0.y;
            Asm[r][q * 8 + 2] = v0.z; Asm[r][q * 8 + 3] = v0.w;
            Asm[r][q * 8 + 4] = v1.x; Asm[r][q * 8 + 5] = v1.y;
            Asm[r][q * 8 + 6] = v1.z; Asm[r][q * 8 + 7] = v1.w;
        }
        {
            int r = tid >> 3, q = tid & 7;
            const float4* bp = (const float4*)&B[(kc * 32 + r) * NDIM + col0];
            float4 v0 = bp[q * 2], v1 = bp[q * 2 + 1];
            Bsm[r][q * 8 + 0] = v0.x; Bsm[r][q * 8 + 1] = v0.y;
            Bsm[r][q * 8 + 2] = v0.z; Bsm[r][q * 8 + 3] = v0.w;
            Bsm[r][q * 8 + 4] = v1.x; Bsm[r][q * 8 + 5] = v1.y;
            Bsm[r][q * 8 + 6] = v1.z; Bsm[r][q * 8 + 7] = v1.w;
        }
        __syncthreads();

        #pragma unroll 8
        for (int m = 0; m < 32; ++m) {
            float ar[4], br[4];
            #pragma unroll
            for (int i = 0; i < 4; ++i) ar[i] = Asm[ty * 4 + i][m];
            #pragma unroll
            for (int j = 0; j < 4; ++j) br[j] = Bsm[m][tx * 4 + j];
            #pragma unroll
            for (int i = 0; i < 4; ++i)
                #pragma unroll
                for (int j = 0; j < 4; ++j) acc[i][j] += ar[i] * br[j];
        }
    }

    #pragma unroll
    for (int i = 0; i < 4; ++i)
        #pragma unroll
        for (int j = 0; j < 4; ++j)
            C[(size_t)(row0 + ty * 4 + i) * NDIM + col0 + tx * 4 + j] = acc[i][j];
}

// ---------------- 3) compose W = M2 diag(e^{i phi}) M1 -----------------------
__global__ void k_compose(const float* __restrict__ phases) {
    __shared__ float sa[8][NDIM];
    __shared__ float sb[8][NDIM];
    int t = threadIdx.x;
    int n0 = blockIdx.x * 8;

    float sp, cp;
    sincosf(phases[t], &sp, &cp);
    #pragma unroll
    for (int r = 0; r < 8; ++r) {
        float m2 = g_M2[(n0 + r) * NDIM + t];
        sa[r][t] = m2 * cp;
        sb[r][t] = m2 * sp;
    }
    __syncthreads();

    float are[8], aim[8];
    #pragma unroll
    for (int r = 0; r < 8; ++r) { are[r] = 0.f; aim[r] = 0.f; }

    for (int m = 0; m < NDIM; ++m) {
        float m1 = g_M1[m * NDIM + t];
        #pragma unroll
        for (int r = 0; r < 8; ++r) {
            are[r] += sa[r][m] * m1;
            aim[r] += sb[r][m] * m1;
        }
    }
    #pragma unroll
    for (int r = 0; r < 8; ++r) {
        g_Wre[(n0 + r) * NDIM + t] = are[r];
        g_Wim[(n0 + r) * NDIM + t] = aim[r];
    }
}

// ---------------- 3b) split W into bf16 hi/lo (re/im interleaved) ------------
__global__ void k_convw() {
    int idx = blockIdx.x * 256 + threadIdx.x;
    int n2 = idx >> 8;
    int k  = idx & 255;
    const float* src = (n2 & 1) ? g_Wim : g_Wre;
    float v = src[(n2 >> 1) * NDIM + k];
    __nv_bfloat16 h = __float2bfloat16(v);
    float lo = v - __bfloat162float(h);
    g_Whi[idx] = h;
    g_Wlo[idx] = __float2bfloat16(lo);
}

// ---------------- 4) fused X split + row norms -------------------------------
__global__ void k_convx_norm(const float4* __restrict__ x4) {
    int w = threadIdx.x >> 5;
    int lane = threadIdx.x & 31;
    int row = blockIdx.x * 8 + w;
    const float4* p = x4 + (size_t)row * 64;
    float4 va = p[lane];
    float4 vb = p[lane + 32];

    float s = va.x * va.x + va.y * va.y + va.z * va.z + va.w * va.w
            + vb.x * vb.x + vb.y * vb.y + vb.z * vb.z + vb.w * vb.w;
    #pragma unroll
    for (int o = 16; o; o >>= 1) s += __shfl_xor_sync(0xffffffffu, s, o);
    if (lane == 0) g_norm2[row] = s;

    __nv_bfloat162* Ph = (__nv_bfloat162*)(g_Xhi + (size_t)row * NDIM);
    __nv_bfloat162* Pl = (__nv_bfloat162*)(g_Xlo + (size_t)row * NDIM);
    #pragma unroll
    for (int half = 0; half < 2; ++half) {
        float4 v = half ? vb : va;
        int base = (lane + half * 32) * 2;
        __nv_bfloat16 h0 = __float2bfloat16(v.x);
        __nv_bfloat16 h1 = __float2bfloat16(v.y);
        __nv_bfloat16 h2 = __float2bfloat16(v.z);
        __nv_bfloat16 h3 = __float2bfloat16(v.w);
        Ph[base + 0] = __nv_bfloat162(h0, h1);
        Ph[base + 1] = __nv_bfloat162(h2, h3);
        Pl[base + 0] = __nv_bfloat162(__float2bfloat16(v.x - __bfloat162float(h0)),
                                      __float2bfloat16(v.y - __bfloat162float(h1)));
        Pl[base + 1] = __nv_bfloat162(__float2bfloat16(v.z - __bfloat162float(h2)),
                                      __float2bfloat16(v.w - __bfloat162float(h3)));
    }
}

// ---------------- 5) classic-MMA GEMM, BK=64, 3-stage cp.async ring ----------
// C-tile 128(M) x 128(N'), 8 warps (2x4), warp tile 64x32.
// 12 stages: 3 split-phases (XhiWhi, XhiWlo, XloWhi) x 4 k-chunks of 64.
// One __syncthreads per stage; load(it+2) -> buf (it+2)%3 == (it-1)%3, whose
// readers all passed this stage's sync. smem row stride 72 bf16 (4r mod 32
// bank walk -> conflict-free ldmatrix).
#define AST   72                         // bf16 row stride
#define TILEB (128 * AST * 2)            // 18432 B per operand tile
#define STGB  (2 * TILEB)                // 36864 B per stage (A+B)
#define GEMM_SMEM (3 * STGB)             // 110592 B

__global__ __launch_bounds__(256, 2) void k_gemm_tc(float* __restrict__ out) {
    extern __shared__ __align__(16) char smem[];
    uint32_t sb = smem_u32(smem);

    int tid = threadIdx.x;
    int wid = tid >> 5, lane = tid & 31;
    int warp_m = wid >> 2;          // 0..1
    int warp_n = wid & 3;           // 0..3
    int mtile = blockIdx.x;         // 0..511
    int ntile = blockIdx.y;         // 0..3

    float acc[4][4][4];
    #pragma unroll
    for (int mt = 0; mt < 4; ++mt)
        #pragma unroll
        for (int nt = 0; nt < 4; ++nt)
            #pragma unroll
            for (int q = 0; q < 4; ++q) acc[mt][nt][q] = 0.f;

    // ldmatrix lane addressing (non-trans for both operands)
    int a_row  = warp_m * 64 + (lane & 15);
    int a_colp = (lane >> 4) * 8;
    int b_rowl = ((lane >> 4) << 3) + (lane & 7);
    int b_colp = ((lane >> 3) & 1) * 8;

    // staging: 128 rows x 8 chunks(16B) per tile, 4 iters x 256 threads
    int ld_r = tid >> 3;            // row 0..31 (+32*i)
    int ld_c = tid & 7;             // chunk 0..7
    uint32_t st_off = (uint32_t)(ld_r * (AST * 2) + ld_c * 16);

    auto load_stage = [&](int it, int buf) {
        int phase = it >> 2;
        int kc = (it & 3) * 64;
        const __nv_bfloat16* Xs = (phase == 2) ? g_Xlo : g_Xhi;
        const __nv_bfloat16* Ws = (phase == 1) ? g_Wlo : g_Whi;
        uint32_t ab = sb + (uint32_t)buf * STGB;
        uint32_t bb = ab + TILEB;
        #pragma unroll
        for (int i = 0; i < 4; ++i) {
            int r = ld_r + i * 32;
            uint32_t so = st_off + (uint32_t)(i * 32 * AST * 2);
            cp16(ab + so, Xs + (size_t)(mtile * 128 + r) * 256 + kc + ld_c * 8);
            cp16(bb + so, Ws + (size_t)(ntile * 128 + r) * 256 + kc + ld_c * 8);
        }
    };

    load_stage(0, 0); cp_commit();
    load_stage(1, 1); cp_commit();

    for (int it = 0; it < 12; ++it) {
        int buf = it - (it / 3) * 3;        // it % 3
        if (it < 11) cp_wait<1>(); else cp_wait<0>();
        __syncthreads();
        if (it + 2 < 12) {
            int nb = (it + 2) - ((it + 2) / 3) * 3;
            load_stage(it + 2, nb);
            cp_commit();
        }

        uint32_t abuf = sb + (uint32_t)buf * STGB;
        uint32_t bbuf = abuf + TILEB;
        #pragma unroll
        for (int kk = 0; kk < 4; ++kk) {
            uint32_t afrag[4][4];
            #pragma unroll
            for (int mt = 0; mt < 4; ++mt) {
                uint32_t addr = abuf +
                    (uint32_t)(((a_row + mt * 16) * AST + kk * 16 + a_colp) * 2);
                ldsm_x4(afrag[mt][0], afrag[mt][1], afrag[mt][2], afrag[mt][3], addr);
            }
            uint32_t bfrag[2][4];
            #pragma unroll
            for (int nb = 0; nb < 2; ++nb) {
                uint32_t addr = bbuf +
                    (uint32_t)(((warp_n * 32 + nb * 16 + b_rowl) * AST + kk * 16 + b_colp) * 2);
                ldsm_x4(bfrag[nb][0], bfrag[nb][1], bfrag[nb][2], bfrag[nb][3], addr);
            }
            #pragma unroll
            for (int mt = 0; mt < 4; ++mt)
                #pragma unroll
                for (int nt = 0; nt < 4; ++nt)
                    mma16816(acc[mt][nt], afrag[mt],
                             bfrag[nt >> 1][(nt & 1) * 2],
                             bfrag[nt >> 1][(nt & 1) * 2 + 1]);
        }
    }

    // epilogue: pair (even,odd) N' columns -> |y|^2 / ||x||^2
    int r0 = mtile * 128 + warp_m * 64 + (lane >> 2);
    int cb = ntile * 64 + warp_n * 16 + (lane & 3);
    #pragma unroll
    for (int mt = 0; mt < 4; ++mt) {
        int row = r0 + mt * 16;
        float inv0 = 1.0f / g_norm2[row];
        float inv8 = 1.0f / g_norm2[row + 8];
        #pragma unroll
        for (int nt = 0; nt < 4; ++nt) {
            int colc = cb + nt * 4;
            float* dd = acc[mt][nt];
            out[(size_t)row * NDIM + colc]       = (dd[0] * dd[0] + dd[1] * dd[1]) * inv0;
            out[(size_t)(row + 8) * NDIM + colc] = (dd[2] * dd[2] + dd[3] * dd[3]) * inv8;
        }
    }
}

// ---------------- launcher ---------------------------------------------------
extern "C" void kernel_launch(void* const* d_in, const int* in_sizes, int n_in,
                              void* d_out, int out_size) {
    const float* x      = (const float*)d_in[0];
    const float* rots1  = (const float*)d_in[1];
    const float* phases = (const float*)d_in[2];
    const float* rots2  = (const float*)d_in[3];
    float* out = (float*)d_out;

    cudaFuncSetAttribute(k_gemm_tc, cudaFuncAttributeMaxDynamicSharedMemorySize,
                         GEMM_SMEM);

    k_sincos<<<(NROT + 255) / 256, 256>>>(rots1, rots2);
    k_build_chunk<<<128, 32>>>();
    k_combine<<<dim3(4, 4, 8), 256>>>(0);
    k_combine<<<dim3(4, 4, 4), 256>>>(1);
    k_combine<<<dim3(4, 4, 2), 256>>>(2);
    k_compose<<<NDIM / 8, NDIM>>>(phases);
    k_convw<<<512, 256>>>();
    k_convx_norm<<<BATCH / 8, 256>>>((const float4*)x);
    k_gemm_tc<<<dim3(BATCH / 128, 4), 256, GEMM_SMEM>>>(out);
}

// round 14
// speedup vs baseline: 5.3915x; 1.1425x over previous
#include <cuda_runtime.h>
#include <cuda_fp16.h>
#include <stdint.h>
#include <math.h>

#define NDIM  256
#define NROT  32640
#define BATCH 65536

// ---------------- scratch (device globals; no allocation allowed) ----------
__device__ float2 g_cs1[NROT];
__device__ float2 g_cs2[NROT];
__device__ float  g_chunks[2 * 8 * NDIM * NDIM];
__device__ float  g_q[2 * 4 * NDIM * NDIM];
__device__ float  g_r[2 * 2 * NDIM * NDIM];
__device__ float  g_M1[NDIM * NDIM];
__device__ float  g_M2[NDIM * NDIM];
__device__ float  g_Wre[NDIM * NDIM];
__device__ float  g_Wim[NDIM * NDIM];
__device__ float  g_norm2[BATCH];

__device__ __half g_Xhi[BATCH * NDIM];             // fp16 hi split of X
__device__ __half g_Xlo[BATCH * NDIM];             // fp16 residual of X
__device__ __half g_Whi[2 * NDIM * NDIM];          // N'=512 (even=Re, odd=Im)

__constant__ int c_bound[9] = {0, 16, 34, 53, 74, 99, 127, 165, 255};

// ---------------- PTX helpers ------------------------------------------------
__device__ __forceinline__ uint32_t smem_u32(const void* p) {
    uint32_t a;
    asm("{ .reg .u64 t; cvta.to.shared.u64 t, %1; cvt.u32.u64 %0, t; }"
        : "=r"(a) : "l"(p));
    return a;
}

__device__ __forceinline__ void cp16(uint32_t dst, const void* src) {
    asm volatile("cp.async.cg.shared.global [%0], [%1], 16;" :: "r"(dst), "l"(src));
}
__device__ __forceinline__ void cp_commit() {
    asm volatile("cp.async.commit_group;");
}
template <int N>
__device__ __forceinline__ void cp_wait() {
    asm volatile("cp.async.wait_group %0;" :: "n"(N));
}

__device__ __forceinline__ void mma16816(float* d, const uint32_t* a,
                                         uint32_t b0, uint32_t b1) {
    asm volatile(
        "mma.sync.aligned.m16n8k16.row.col.f32.f16.f16.f32 "
        "{%0,%1,%2,%3}, {%4,%5,%6,%7}, {%8,%9}, {%0,%1,%2,%3};"
        : "+f"(d[0]), "+f"(d[1]), "+f"(d[2]), "+f"(d[3])
        : "r"(a[0]), "r"(a[1]), "r"(a[2]), "r"(a[3]), "r"(b0), "r"(b1));
}

__device__ __forceinline__ void ldsm_x4(uint32_t& r0, uint32_t& r1,
                                        uint32_t& r2, uint32_t& r3,
                                        uint32_t addr) {
    asm volatile("ldmatrix.sync.aligned.m8n8.x4.shared.b16 {%0,%1,%2,%3}, [%4];"
                 : "=r"(r0), "=r"(r1), "=r"(r2), "=r"(r3) : "r"(addr));
}

// ---------------- 1) cos/sin --------------------------------------------------
__global__ void k_sincos(const float* __restrict__ rots1,
                         const float* __restrict__ rots2) {
    int i = blockIdx.x * blockDim.x + threadIdx.x;
    if (i < NROT) {
        float s, c;
        sincosf(rots1[i], &s, &c);
        g_cs1[i] = make_float2(c, s);
        sincosf(rots2[i], &s, &c);
        g_cs2[i] = make_float2(c, s);
    }
}

// ---------------- 2a) build 8 chunk products per matrix ----------------------
__global__ void k_build_chunk() {
    __shared__ float col[NDIM * 32];
    int t = threadIdx.x;
    int b = blockIdx.x;
    int mat = b >> 6;
    int rem = b & 63;
    int chunk = rem >> 3;
    int cg = rem & 7;
    int c = cg * 32 + t;

    int a = c_bound[chunk];
    int e = c_bound[chunk + 1];

    const float2* __restrict__ cs = mat ? g_cs2 : g_cs1;
    float* __restrict__ P = g_chunks + (size_t)(mat * 8 + chunk) * (NDIM * NDIM);

    for (int r = 0; r < NDIM; ++r)
        col[r * 32 + t] = (r == c) ? 1.0f : 0.0f;

    int ridx = a * 255 - (a * (a - 1)) / 2;
    for (int i = a; i < e; ++i) {
        float acc = col[i * 32 + t];
        #pragma unroll 8
        for (int j = i + 1; j < NDIM; ++j) {
            float2 v = __ldg(&cs[ridx]);
            ++ridx;
            float vj = col[j * 32 + t];
            col[j * 32 + t] = v.y * acc + v.x * vj;
            acc = v.x * acc - v.y * vj;
        }
        col[i * 32 + t] = acc;
    }

    for (int r = 0; r < NDIM; ++r)
        P[r * NDIM + c] = col[r * 32 + t];
}

// ---------------- 2b) combine chunks: register-prefetch pipeline -------------
// grid (4,4,z): 64x64 C tile, 256 threads, 4x4/thread, K=256.
// Next kc's global loads are issued into registers BEFORE this kc's compute,
// hiding DRAM latency. Scalar smem stores (padded strides not 16B-aligned).
__global__ __launch_bounds__(256) void k_combine(int step) {
    __shared__ float Asm[64][33];
    __shared__ float Bsm[32][65];

    int z = blockIdx.z;
    const float *A, *B;
    float* C;
    if (step == 0) {
        int mat = z >> 2, p = z & 3;
        A = g_chunks + (size_t)(mat * 8 + 2 * p + 1) * (NDIM * NDIM);
        B = g_chunks + (size_t)(mat * 8 + 2 * p) * (NDIM * NDIM);
        C = g_q + (size_t)(mat * 4 + p) * (NDIM * NDIM);
    } else if (step == 1) {
        int mat = z >> 1, p = z & 1;
        A = g_q + (size_t)(mat * 4 + 2 * p + 1) * (NDIM * NDIM);
        B = g_q + (size_t)(mat * 4 + 2 * p) * (NDIM * NDIM);
        C = g_r + (size_t)(mat * 2 + p) * (NDIM * NDIM);
    } else {
        int mat = z;
        A = g_r + (size_t)(mat * 2 + 1) * (NDIM * NDIM);
        B = g_r + (size_t)(mat * 2 + 0) * (NDIM * NDIM);
        C = mat ? g_M2 : g_M1;
    }

    int tid = threadIdx.x;
    int tx = tid & 15, ty = tid >> 4;
    int row0 = blockIdx.y * 64;
    int col0 = blockIdx.x * 64;

    int ar = tid >> 2, aq = tid & 3;
    int br = tid >> 3, bq = tid & 7;

    float acc[4][4];
    #pragma unroll
    for (int i = 0; i < 4; ++i)
        #pragma unroll
        for (int j = 0; j < 4; ++j) acc[i][j] = 0.f;

    float4 pa0, pa1, pb0, pb1;
    {
        const float4* ap = (const float4*)&A[(row0 + ar) * NDIM];
        pa0 = ap[aq * 2]; pa1 = ap[aq * 2 + 1];
        const float4* bp = (const float4*)&B[(size_t)br * NDIM + col0];
        pb0 = bp[bq * 2]; pb1 = bp[bq * 2 + 1];
    }

    for (int kc = 0; kc < 8; ++kc) {
        __syncthreads();
        Asm[ar][aq * 8 + 0] = pa0.x; Asm[ar][aq * 8 + 1] = pa0.y;
        Asm[ar][aq * 8 + 2] = pa0.z; Asm[ar][aq * 8 + 3] = pa0.w;
        Asm[ar][aq * 8 + 4] = pa1.x; Asm[ar][aq * 8 + 5] = pa1.y;
        Asm[ar][aq * 8 + 6] = pa1.z; Asm[ar][aq * 8 + 7] = pa1.w;
        Bsm[br][bq * 8 + 0] = pb0.x; Bsm[br][bq * 8 + 1] = pb0.y;
        Bsm[br][bq * 8 + 2] = pb0.z; Bsm[br][bq * 8 + 3] = pb0.w;
        Bsm[br][bq * 8 + 4] = pb1.x; Bsm[br][bq * 8 + 5] = pb1.y;
        Bsm[br][bq * 8 + 6] = pb1.z; Bsm[br][bq * 8 + 7] = pb1.w;
        __syncthreads();

        if (kc < 7) {
            const float4* ap = (const float4*)&A[(row0 + ar) * NDIM + (kc + 1) * 32];
            pa0 = ap[aq * 2]; pa1 = ap[aq * 2 + 1];
            const float4* bp = (const float4*)&B[(size_t)((kc + 1) * 32 + br) * NDIM + col0];
            pb0 = bp[bq * 2]; pb1 = bp[bq * 2 + 1];
        }

        #pragma unroll 8
        for (int m = 0; m < 32; ++m) {
            float arr[4], brr[4];
            #pragma unroll
            for (int i = 0; i < 4; ++i) arr[i] = Asm[ty * 4 + i][m];
            #pragma unroll
            for (int j = 0; j < 4; ++j) brr[j] = Bsm[m][tx * 4 + j];
            #pragma unroll
            for (int i = 0; i < 4; ++i)
                #pragma unroll
                for (int j = 0; j < 4; ++j) acc[i][j] += arr[i] * brr[j];
        }
    }

    #pragma unroll
    for (int i = 0; i < 4; ++i)
        #pragma unroll
        for (int j = 0; j < 4; ++j)
            C[(size_t)(row0 + ty * 4 + i) * NDIM + col0 + tx * 4 + j] = acc[i][j];
}

// ---------------- 3) compose W = M2 diag(e^{i phi}) M1 -----------------------
__global__ void k_compose(const float* __restrict__ phases) {
    __shared__ float sa[8][NDIM];
    __shared__ float sb[8][NDIM];
    int t = threadIdx.x;
    int n0 = blockIdx.x * 8;

    float sp, cp;
    sincosf(phases[t], &sp, &cp);
    #pragma unroll
    for (int r = 0; r < 8; ++r) {
        float m2 = g_M2[(n0 + r) * NDIM + t];
        sa[r][t] = m2 * cp;
        sb[r][t] = m2 * sp;
    }
    __syncthreads();

    float are[8], aim[8];
    #pragma unroll
    for (int r = 0; r < 8; ++r) { are[r] = 0.f; aim[r] = 0.f; }

    for (int m = 0; m < NDIM; ++m) {
        float m1 = g_M1[m * NDIM + t];
        #pragma unroll
        for (int r = 0; r < 8; ++r) {
            are[r] += sa[r][m] * m1;
            aim[r] += sb[r][m] * m1;
        }
    }
    #pragma unroll
    for (int r = 0; r < 8; ++r) {
        g_Wre[(n0 + r) * NDIM + t] = are[r];
        g_Wim[(n0 + r) * NDIM + t] = aim[r];
    }
}

// ---------------- 3b) W -> fp16 (re/im interleaved rows) ---------------------
__global__ void k_convw() {
    int idx = blockIdx.x * 256 + threadIdx.x;   // 0 .. 131071
    int n2 = idx >> 8;
    int k  = idx & 255;
    const float* src = (n2 & 1) ? g_Wim : g_Wre;
    g_Whi[idx] = __float2half(src[(n2 >> 1) * NDIM + k]);
}

// ---------------- 4) fused X fp16 hi/lo split + row norms --------------------
__global__ void k_convx_norm(const float4* __restrict__ x4) {
    int w = threadIdx.x >> 5;
    int lane = threadIdx.x & 31;
    int row = blockIdx.x * 8 + w;
    const float4* p = x4 + (size_t)row * 64;
    float4 va = p[lane];
    float4 vb = p[lane + 32];

    float s = va.x * va.x + va.y * va.y + va.z * va.z + va.w * va.w
            + vb.x * vb.x + vb.y * vb.y + vb.z * vb.z + vb.w * vb.w;
    #pragma unroll
    for (int o = 16; o; o >>= 1) s += __shfl_xor_sync(0xffffffffu, s, o);
    if (lane == 0) g_norm2[row] = s;

    __half2* Ph = (__half2*)(g_Xhi + (size_t)row * NDIM);
    __half2* Pl = (__half2*)(g_Xlo + (size_t)row * NDIM);
    #pragma unroll
    for (int half = 0; half < 2; ++half) {
        float4 v = half ? vb : va;
        int base = (lane + half * 32) * 2;
        __half h0 = __float2half(v.x);
        __half h1 = __float2half(v.y);
        __half h2 = __float2half(v.z);
        __half h3 = __float2half(v.w);
        Ph[base + 0] = __halves2half2(h0, h1);
        Ph[base + 1] = __halves2half2(h2, h3);
        Pl[base + 0] = __halves2half2(__float2half(v.x - __half2float(h0)),
                                      __float2half(v.y - __half2float(h1)));
        Pl[base + 1] = __halves2half2(__float2half(v.z - __half2float(h2)),
                                      __float2half(v.w - __half2float(h3)));
    }
}

// ---------------- 5) classic-MMA GEMM, fp16 2-pass, BK=64, 3-stage ring ------
// C-tile 128(M) x 128(N'), 8 warps (2x4), warp tile 64x32.
// 8 stages: 2 phases (Xhi*Whi, Xlo*Whi) x 4 k-chunks of 64.
// y = (Xhi + Xlo) * Whi^T  -> dropped term x*Wlo ~ 2.8e-4 (fits 1e-3 budget).
#define AST   72                         // fp16 row stride
#define TILEB (128 * AST * 2)            // 18432 B per operand tile
#define STGB  (2 * TILEB)                // 36864 B per stage (A+B)
#define GEMM_SMEM (3 * STGB)             // 110592 B

__global__ __launch_bounds__(256, 2) void k_gemm_tc(float* __restrict__ out) {
    extern __shared__ __align__(16) char smem[];
    uint32_t sb = smem_u32(smem);

    int tid = threadIdx.x;
    int wid = tid >> 5, lane = tid & 31;
    int warp_m = wid >> 2;          // 0..1
    int warp_n = wid & 3;           // 0..3
    int mtile = blockIdx.x;         // 0..511
    int ntile = blockIdx.y;         // 0..3

    float acc[4][4][4];
    #pragma unroll
    for (int mt = 0; mt < 4; ++mt)
        #pragma unroll
        for (int nt = 0; nt < 4; ++nt)
            #pragma unroll
            for (int q = 0; q < 4; ++q) acc[mt][nt][q] = 0.f;

    int a_row  = warp_m * 64 + (lane & 15);
    int a_colp = (lane >> 4) * 8;
    int b_rowl = ((lane >> 4) << 3) + (lane & 7);
    int b_colp = ((lane >> 3) & 1) * 8;

    int ld_r = tid >> 3;            // row 0..31 (+32*i)
    int ld_c = tid & 7;             // chunk 0..7
    uint32_t st_off = (uint32_t)(ld_r * (AST * 2) + ld_c * 16);

    auto load_stage = [&](int it, int buf) {
        int phase = it >> 2;
        int kc = (it & 3) * 64;
        const __half* Xs = phase ? g_Xlo : g_Xhi;
        uint32_t ab = sb + (uint32_t)buf * STGB;
        uint32_t bb = ab + TILEB;
        #pragma unroll
        for (int i = 0; i < 4; ++i) {
            int r = ld_r + i * 32;
            uint32_t so = st_off + (uint32_t)(i * 32 * AST * 2);
            cp16(ab + so, Xs + (size_t)(mtile * 128 + r) * 256 + kc + ld_c * 8);
            cp16(bb + so, g_Whi + (size_t)(ntile * 128 + r) * 256 + kc + ld_c * 8);
        }
    };

    load_stage(0, 0); cp_commit();
    load_stage(1, 1); cp_commit();

    for (int it = 0; it < 8; ++it) {
        int buf = it - (it / 3) * 3;        // it % 3
        if (it < 7) cp_wait<1>(); else cp_wait<0>();
        __syncthreads();
        if (it + 2 < 8) {
            int nb = (it + 2) - ((it + 2) / 3) * 3;
            load_stage(it + 2, nb);
            cp_commit();
        }

        uint32_t abuf = sb + (uint32_t)buf * STGB;
        uint32_t bbuf = abuf + TILEB;
        #pragma unroll
        for (int kk = 0; kk < 4; ++kk) {
            uint32_t afrag[4][4];
            #pragma unroll
            for (int mt = 0; mt < 4; ++mt) {
                uint32_t addr = abuf +
                    (uint32_t)(((a_row + mt * 16) * AST + kk * 16 + a_colp) * 2);
                ldsm_x4(afrag[mt][0], afrag[mt][1], afrag[mt][2], afrag[mt][3], addr);
            }
            uint32_t bfrag[2][4];
            #pragma unroll
            for (int nb = 0; nb < 2; ++nb) {
                uint32_t addr = bbuf +
                    (uint32_t)(((warp_n * 32 + nb * 16 + b_rowl) * AST + kk * 16 + b_colp) * 2);
                ldsm_x4(bfrag[nb][0], bfrag[nb][1], bfrag[nb][2], bfrag[nb][3], addr);
            }
            #pragma unroll
            for (int mt = 0; mt < 4; ++mt)
                #pragma unroll
                for (int nt = 0; nt < 4; ++nt)
                    mma16816(acc[mt][nt], afrag[mt],
                             bfrag[nt >> 1][(nt & 1) * 2],
                             bfrag[nt >> 1][(nt & 1) * 2 + 1]);
        }
    }

    // epilogue: pair (even,odd) N' columns -> |y|^2 / ||x||^2
    int r0 = mtile * 128 + warp_m * 64 + (lane >> 2);
    int cb = ntile * 64 + warp_n * 16 + (lane & 3);
    #pragma unroll
    for (int mt = 0; mt < 4; ++mt) {
        int row = r0 + mt * 16;
        float inv0 = 1.0f / g_norm2[row];
        float inv8 = 1.0f / g_norm2[row + 8];
        #pragma unroll
        for (int nt = 0; nt < 4; ++nt) {
            int colc = cb + nt * 4;
            float* dd = acc[mt][nt];
            out[(size_t)row * NDIM + colc]       = (dd[0] * dd[0] + dd[1] * dd[1]) * inv0;
            out[(size_t)(row + 8) * NDIM + colc] = (dd[2] * dd[2] + dd[3] * dd[3]) * inv8;
        }
    }
}

// ---------------- launcher ---------------------------------------------------
extern "C" void kernel_launch(void* const* d_in, const int* in_sizes, int n_in,
                              void* d_out, int out_size) {
    const float* x      = (const float*)d_in[0];
    const float* rots1  = (const float*)d_in[1];
    const float* phases = (const float*)d_in[2];
    const float* rots2  = (const float*)d_in[3];
    float* out = (float*)d_out;

    cudaFuncSetAttribute(k_gemm_tc, cudaFuncAttributeMaxDynamicSharedMemorySize,
                         GEMM_SMEM);

    k_sincos<<<(NROT + 255) / 256, 256>>>(rots1, rots2);
    k_build_chunk<<<128, 32>>>();
    k_combine<<<dim3(4, 4, 8), 256>>>(0);
    k_combine<<<dim3(4, 4, 4), 256>>>(1);
    k_combine<<<dim3(4, 4, 2), 256>>>(2);
    k_compose<<<NDIM / 8, NDIM>>>(phases);
    k_convw<<<512, 256>>>();
    k_convx_norm<<<BATCH / 8, 256>>>((const float4*)x);
    k_gemm_tc<<<dim3(BATCH / 128, 4), 256, GEMM_SMEM>>>(out);
}

// round 15
// speedup vs baseline: 6.2454x; 1.1584x over previous
#include <cuda_runtime.h>
#include <cuda_fp16.h>
#include <stdint.h>
#include <math.h>

#define NDIM  256
#define NROT  32640
#define BATCH 65536

// ---------------- scratch (device globals; no allocation allowed) ----------
__device__ float2 g_cs1[NROT];
__device__ float2 g_cs2[NROT];
__device__ float  g_chunks[2 * 8 * NDIM * NDIM];
__device__ float  g_q[2 * 4 * NDIM * NDIM];
__device__ float  g_r[2 * 2 * NDIM * NDIM];
__device__ float  g_M1[NDIM * NDIM];
__device__ float  g_M2[NDIM * NDIM];
__device__ float  g_norm2[BATCH];

__device__ __half g_Xhi[BATCH * NDIM];             // fp16 X
__device__ __half g_Whi[2 * NDIM * NDIM];          // N'=512 (even=Re, odd=Im)

__constant__ int c_bound[9] = {0, 16, 34, 53, 74, 99, 127, 165, 255};

// ---------------- PTX helpers ------------------------------------------------
__device__ __forceinline__ uint32_t smem_u32(const void* p) {
    uint32_t a;
    asm("{ .reg .u64 t; cvta.to.shared.u64 t, %1; cvt.u32.u64 %0, t; }"
        : "=r"(a) : "l"(p));
    return a;
}

__device__ __forceinline__ void cp16(uint32_t dst, const void* src) {
    asm volatile("cp.async.cg.shared.global [%0], [%1], 16;" :: "r"(dst), "l"(src));
}
__device__ __forceinline__ void cp_commit() {
    asm volatile("cp.async.commit_group;");
}
template <int N>
__device__ __forceinline__ void cp_wait() {
    asm volatile("cp.async.wait_group %0;" :: "n"(N));
}

__device__ __forceinline__ void mma16816(float* d, const uint32_t* a,
                                         uint32_t b0, uint32_t b1) {
    asm volatile(
        "mma.sync.aligned.m16n8k16.row.col.f32.f16.f16.f32 "
        "{%0,%1,%2,%3}, {%4,%5,%6,%7}, {%8,%9}, {%0,%1,%2,%3};"
        : "+f"(d[0]), "+f"(d[1]), "+f"(d[2]), "+f"(d[3])
        : "r"(a[0]), "r"(a[1]), "r"(a[2]), "r"(a[3]), "r"(b0), "r"(b1));
}

__device__ __forceinline__ void ldsm_x4(uint32_t& r0, uint32_t& r1,
                                        uint32_t& r2, uint32_t& r3,
                                        uint32_t addr) {
    asm volatile("ldmatrix.sync.aligned.m8n8.x4.shared.b16 {%0,%1,%2,%3}, [%4];"
                 : "=r"(r0), "=r"(r1), "=r"(r2), "=r"(r3) : "r"(addr));
}

// ---------------- 1) cos/sin --------------------------------------------------
__global__ void k_sincos(const float* __restrict__ rots1,
                         const float* __restrict__ rots2) {
    int i = blockIdx.x * blockDim.x + threadIdx.x;
    if (i < NROT) {
        float s, c;
        sincosf(rots1[i], &s, &c);
        g_cs1[i] = make_float2(c, s);
        sincosf(rots2[i], &s, &c);
        g_cs2[i] = make_float2(c, s);
    }
}

// ---------------- 2a) build 8 chunk products per matrix ----------------------
__global__ void k_build_chunk() {
    __shared__ float col[NDIM * 32];
    int t = threadIdx.x;
    int b = blockIdx.x;
    int mat = b >> 6;
    int rem = b & 63;
    int chunk = rem >> 3;
    int cg = rem & 7;
    int c = cg * 32 + t;

    int a = c_bound[chunk];
    int e = c_bound[chunk + 1];

    const float2* __restrict__ cs = mat ? g_cs2 : g_cs1;
    float* __restrict__ P = g_chunks + (size_t)(mat * 8 + chunk) * (NDIM * NDIM);

    for (int r = 0; r < NDIM; ++r)
        col[r * 32 + t] = (r == c) ? 1.0f : 0.0f;

    int ridx = a * 255 - (a * (a - 1)) / 2;
    for (int i = a; i < e; ++i) {
        float acc = col[i * 32 + t];
        #pragma unroll 8
        for (int j = i + 1; j < NDIM; ++j) {
            float2 v = __ldg(&cs[ridx]);
            ++ridx;
            float vj = col[j * 32 + t];
            col[j * 32 + t] = v.y * acc + v.x * vj;
            acc = v.x * acc - v.y * vj;
        }
        col[i * 32 + t] = acc;
    }

    for (int r = 0; r < NDIM; ++r)
        P[r * NDIM + c] = col[r * 32 + t];
}

// ---------------- 2b) combine chunks: register-prefetch pipeline -------------
__global__ __launch_bounds__(256) void k_combine(int step) {
    __shared__ float Asm[64][33];
    __shared__ float Bsm[32][65];

    int z = blockIdx.z;
    const float *A, *B;
    float* C;
    if (step == 0) {
        int mat = z >> 2, p = z & 3;
        A = g_chunks + (size_t)(mat * 8 + 2 * p + 1) * (NDIM * NDIM);
        B = g_chunks + (size_t)(mat * 8 + 2 * p) * (NDIM * NDIM);
        C = g_q + (size_t)(mat * 4 + p) * (NDIM * NDIM);
    } else if (step == 1) {
        int mat = z >> 1, p = z & 1;
        A = g_q + (size_t)(mat * 4 + 2 * p + 1) * (NDIM * NDIM);
        B = g_q + (size_t)(mat * 4 + 2 * p) * (NDIM * NDIM);
        C = g_r + (size_t)(mat * 2 + p) * (NDIM * NDIM);
    } else {
        int mat = z;
        A = g_r + (size_t)(mat * 2 + 1) * (NDIM * NDIM);
        B = g_r + (size_t)(mat * 2 + 0) * (NDIM * NDIM);
        C = mat ? g_M2 : g_M1;
    }

    int tid = threadIdx.x;
    int tx = tid & 15, ty = tid >> 4;
    int row0 = blockIdx.y * 64;
    int col0 = blockIdx.x * 64;

    int ar = tid >> 2, aq = tid & 3;
    int br = tid >> 3, bq = tid & 7;

    float acc[4][4];
    #pragma unroll
    for (int i = 0; i < 4; ++i)
        #pragma unroll
        for (int j = 0; j < 4; ++j) acc[i][j] = 0.f;

    float4 pa0, pa1, pb0, pb1;
    {
        const float4* ap = (const float4*)&A[(row0 + ar) * NDIM];
        pa0 = ap[aq * 2]; pa1 = ap[aq * 2 + 1];
        const float4* bp = (const float4*)&B[(size_t)br * NDIM + col0];
        pb0 = bp[bq * 2]; pb1 = bp[bq * 2 + 1];
    }

    for (int kc = 0; kc < 8; ++kc) {
        __syncthreads();
        Asm[ar][aq * 8 + 0] = pa0.x; Asm[ar][aq * 8 + 1] = pa0.y;
        Asm[ar][aq * 8 + 2] = pa0.z; Asm[ar][aq * 8 + 3] = pa0.w;
        Asm[ar][aq * 8 + 4] = pa1.x; Asm[ar][aq * 8 + 5] = pa1.y;
        Asm[ar][aq * 8 + 6] = pa1.z; Asm[ar][aq * 8 + 7] = pa1.w;
        Bsm[br][bq * 8 + 0] = pb0.x; Bsm[br][bq * 8 + 1] = pb0.y;
        Bsm[br][bq * 8 + 2] = pb0.z; Bsm[br][bq * 8 + 3] = pb0.w;
        Bsm[br][bq * 8 + 4] = pb1.x; Bsm[br][bq * 8 + 5] = pb1.y;
        Bsm[br][bq * 8 + 6] = pb1.z; Bsm[br][bq * 8 + 7] = pb1.w;
        __syncthreads();

        if (kc < 7) {
            const float4* ap = (const float4*)&A[(row0 + ar) * NDIM + (kc + 1) * 32];
            pa0 = ap[aq * 2]; pa1 = ap[aq * 2 + 1];
            const float4* bp = (const float4*)&B[(size_t)((kc + 1) * 32 + br) * NDIM + col0];
            pb0 = bp[bq * 2]; pb1 = bp[bq * 2 + 1];
        }

        #pragma unroll 8
        for (int m = 0; m < 32; ++m) {
            float arr[4], brr[4];
            #pragma unroll
            for (int i = 0; i < 4; ++i) arr[i] = Asm[ty * 4 + i][m];
            #pragma unroll
            for (int j = 0; j < 4; ++j) brr[j] = Bsm[m][tx * 4 + j];
            #pragma unroll
            for (int i = 0; i < 4; ++i)
                #pragma unroll
                for (int j = 0; j < 4; ++j) acc[i][j] += arr[i] * brr[j];
        }
    }

    #pragma unroll
    for (int i = 0; i < 4; ++i)
        #pragma unroll
        for (int j = 0; j < 4; ++j)
            C[(size_t)(row0 + ty * 4 + i) * NDIM + col0 + tx * 4 + j] = acc[i][j];
}

// ---------------- 3) compose W = M2 diag(e^{i phi}) M1 -> fp16 interleaved ---
// Writes g_Whi directly: row 2n = Re(W[n]), row 2n+1 = Im(W[n]), k contiguous.
__global__ void k_compose(const float* __restrict__ phases) {
    __shared__ float sa[8][NDIM];
    __shared__ float sb[8][NDIM];
    int t = threadIdx.x;
    int n0 = blockIdx.x * 8;

    float sp, cp;
    sincosf(phases[t], &sp, &cp);
    #pragma unroll
    for (int r = 0; r < 8; ++r) {
        float m2 = g_M2[(n0 + r) * NDIM + t];
        sa[r][t] = m2 * cp;
        sb[r][t] = m2 * sp;
    }
    __syncthreads();

    float are[8], aim[8];
    #pragma unroll
    for (int r = 0; r < 8; ++r) { are[r] = 0.f; aim[r] = 0.f; }

    for (int m = 0; m < NDIM; ++m) {
        float m1 = g_M1[m * NDIM + t];
        #pragma unroll
        for (int r = 0; r < 8; ++r) {
            are[r] += sa[r][m] * m1;
            aim[r] += sb[r][m] * m1;
        }
    }
    #pragma unroll
    for (int r = 0; r < 8; ++r) {
        int n = n0 + r;
        g_Whi[(size_t)(2 * n) * NDIM + t]     = __float2half(are[r]);
        g_Whi[(size_t)(2 * n + 1) * NDIM + t] = __float2half(aim[r]);
    }
}

// ---------------- 4) fused X fp16 conversion + row norms ---------------------
__global__ void k_convx_norm(const float4* __restrict__ x4) {
    int w = threadIdx.x >> 5;
    int lane = threadIdx.x & 31;
    int row = blockIdx.x * 8 + w;
    const float4* p = x4 + (size_t)row * 64;
    float4 va = p[lane];
    float4 vb = p[lane + 32];

    float s = va.x * va.x + va.y * va.y + va.z * va.z + va.w * va.w
            + vb.x * vb.x + vb.y * vb.y + vb.z * vb.z + vb.w * vb.w;
    #pragma unroll
    for (int o = 16; o; o >>= 1) s += __shfl_xor_sync(0xffffffffu, s, o);
    if (lane == 0) g_norm2[row] = s;

    __half2* Ph = (__half2*)(g_Xhi + (size_t)row * NDIM);
    #pragma unroll
    for (int half = 0; half < 2; ++half) {
        float4 v = half ? vb : va;
        int base = (lane + half * 32) * 2;
        Ph[base + 0] = __halves2half2(__float2half(v.x), __float2half(v.y));
        Ph[base + 1] = __halves2half2(__float2half(v.z), __float2half(v.w));
    }
}

// ---------------- 5) classic-MMA GEMM, fp16 1-pass, BK=64, 3-stage ring ------
// C-tile 128(M) x 128(N'), 8 warps (2x4), warp tile 64x32.
// 4 stages = 4 k-chunks of 64 (single pass: y = Xhi * Whi^T).
#define AST   72                         // fp16 row stride
#define TILEB (128 * AST * 2)            // 18432 B per operand tile
#define STGB  (2 * TILEB)                // 36864 B per stage (A+B)
#define GEMM_SMEM (3 * STGB)             // 110592 B

__global__ __launch_bounds__(256, 2) void k_gemm_tc(float* __restrict__ out) {
    extern __shared__ __align__(16) char smem[];
    uint32_t sb = smem_u32(smem);

    int tid = threadIdx.x;
    int wid = tid >> 5, lane = tid & 31;
    int warp_m = wid >> 2;          // 0..1
    int warp_n = wid & 3;           // 0..3
    int mtile = blockIdx.x;         // 0..511
    int ntile = blockIdx.y;         // 0..3

    float acc[4][4][4];
    #pragma unroll
    for (int mt = 0; mt < 4; ++mt)
        #pragma unroll
        for (int nt = 0; nt < 4; ++nt)
            #pragma unroll
            for (int q = 0; q < 4; ++q) acc[mt][nt][q] = 0.f;

    int a_row  = warp_m * 64 + (lane & 15);
    int a_colp = (lane >> 4) * 8;
    int b_rowl = ((lane >> 4) << 3) + (lane & 7);
    int b_colp = ((lane >> 3) & 1) * 8;

    int ld_r = tid >> 3;            // row 0..31 (+32*i)
    int ld_c = tid & 7;             // chunk 0..7
    uint32_t st_off = (uint32_t)(ld_r * (AST * 2) + ld_c * 16);

    auto load_stage = [&](int it, int buf) {
        int kc = it * 64;
        uint32_t ab = sb + (uint32_t)buf * STGB;
        uint32_t bb = ab + TILEB;
        #pragma unroll
        for (int i = 0; i < 4; ++i) {
            int r = ld_r + i * 32;
            uint32_t so = st_off + (uint32_t)(i * 32 * AST * 2);
            cp16(ab + so, g_Xhi + (size_t)(mtile * 128 + r) * 256 + kc + ld_c * 8);
            cp16(bb + so, g_Whi + (size_t)(ntile * 128 + r) * 256 + kc + ld_c * 8);
        }
    };

    load_stage(0, 0); cp_commit();
    load_stage(1, 1); cp_commit();

    for (int it = 0; it < 4; ++it) {
        int buf = it - (it / 3) * 3;        // it % 3
        if (it < 3) cp_wait<1>(); else cp_wait<0>();
        __syncthreads();
        if (it + 2 < 4) {
            int nb = (it + 2) - ((it + 2) / 3) * 3;
            load_stage(it + 2, nb);
            cp_commit();
        }

        uint32_t abuf = sb + (uint32_t)buf * STGB;
        uint32_t bbuf = abuf + TILEB;
        #pragma unroll
        for (int kk = 0; kk < 4; ++kk) {
            uint32_t afrag[4][4];
            #pragma unroll
            for (int mt = 0; mt < 4; ++mt) {
                uint32_t addr = abuf +
                    (uint32_t)(((a_row + mt * 16) * AST + kk * 16 + a_colp) * 2);
                ldsm_x4(afrag[mt][0], afrag[mt][1], afrag[mt][2], afrag[mt][3], addr);
            }
            uint32_t bfrag[2][4];
            #pragma unroll
            for (int nb = 0; nb < 2; ++nb) {
                uint32_t addr = bbuf +
                    (uint32_t)(((warp_n * 32 + nb * 16 + b_rowl) * AST + kk * 16 + b_colp) * 2);
                ldsm_x4(bfrag[nb][0], bfrag[nb][1], bfrag[nb][2], bfrag[nb][3], addr);
            }
            #pragma unroll
            for (int mt = 0; mt < 4; ++mt)
                #pragma unroll
                for (int nt = 0; nt < 4; ++nt)
                    mma16816(acc[mt][nt], afrag[mt],
                             bfrag[nt >> 1][(nt & 1) * 2],
                             bfrag[nt >> 1][(nt & 1) * 2 + 1]);
        }
    }

    // epilogue: pair (even,odd) N' columns -> |y|^2 / ||x||^2
    int r0 = mtile * 128 + warp_m * 64 + (lane >> 2);
    int cb = ntile * 64 + warp_n * 16 + (lane & 3);
    #pragma unroll
    for (int mt = 0; mt < 4; ++mt) {
        int row = r0 + mt * 16;
        float inv0 = 1.0f / g_norm2[row];
        float inv8 = 1.0f / g_norm2[row + 8];
        #pragma unroll
        for (int nt = 0; nt < 4; ++nt) {
            int colc = cb + nt * 4;
            float* dd = acc[mt][nt];
            out[(size_t)row * NDIM + colc]       = (dd[0] * dd[0] + dd[1] * dd[1]) * inv0;
            out[(size_t)(row + 8) * NDIM + colc] = (dd[2] * dd[2] + dd[3] * dd[3]) * inv8;
        }
    }
}

// ---------------- launcher ---------------------------------------------------
extern "C" void kernel_launch(void* const* d_in, const int* in_sizes, int n_in,
                              void* d_out, int out_size) {
    const float* x      = (const float*)d_in[0];
    const float* rots1  = (const float*)d_in[1];
    const float* phases = (const float*)d_in[2];
    const float* rots2  = (const float*)d_in[3];
    float* out = (float*)d_out;

    cudaFuncSetAttribute(k_gemm_tc, cudaFuncAttributeMaxDynamicSharedMemorySize,
                         GEMM_SMEM);

    k_sincos<<<(NROT + 255) / 256, 256>>>(rots1, rots2);
    k_build_chunk<<<128, 32>>>();
    k_combine<<<dim3(4, 4, 8), 256>>>(0);
    k_combine<<<dim3(4, 4, 4), 256>>>(1);
    k_combine<<<dim3(4, 4, 2), 256>>>(2);
    k_compose<<<NDIM / 8, NDIM>>>(phases);
    k_convx_norm<<<BATCH / 8, 256>>>((const float4*)x);
    k_gemm_tc<<<dim3(BATCH / 128, 4), 256, GEMM_SMEM>>>(out);
}